// round 8
// baseline (speedup 1.0000x reference)
#include <cuda_runtime.h>
#include <math.h>

#define Bdim 4
#define Ndim 48
#define Rdim 16
#define Tdim 33
#define NCdim 80
#define NIdim 5
#define NN (Ndim * Ndim)          // 2304
#define NEGV -1000.0f
#define PR 36                     // prep rows per CTA
#define NTHREADS 288
#define NBLOCKS (NCdim * Bdim)    // 320

// g_M[b,t][u*48+v] = trans[b,u,v,t]
__device__ float g_M[Bdim * Tdim * NN];
// scratch: exp(path score) per [b, c, xy]
__device__ float g_scratch[Bdim * NCdim * NN];

// ---- sense-reversing grid barrier (all CTAs co-resident by construction) ----
__device__ unsigned g_bar_count = 0;
__device__ unsigned g_bar_gen   = 0;

__device__ __forceinline__ void grid_barrier(unsigned nb)
{
    __syncthreads();
    if (threadIdx.x == 0) {
        __threadfence();
        const unsigned gen = *(volatile unsigned*)&g_bar_gen;
        if (atomicAdd(&g_bar_count, 1u) == nb - 1u) {
            g_bar_count = 0;
            __threadfence();
            *(volatile unsigned*)&g_bar_gen = gen + 1u;
        } else {
            while (*(volatile unsigned*)&g_bar_gen == gen) {}
        }
        __threadfence();
    }
    __syncthreads();
}

__global__ __launch_bounds__(NTHREADS, 3)   // 3/SM guarantee: regs<=75, no spills
void fused_kernel(const float* __restrict__ trans,
                  const int*   __restrict__ rules,
                  const int*   __restrict__ type_mask,
                  const float* __restrict__ weights,
                  const float* __restrict__ biases,
                  float*       __restrict__ out)
{
    __shared__ float P[NN];                    // prep tile / hop0^T / hop2
    __shared__ float Q[NN];                    // hop1 / S^T
    __shared__ float Tpad[Ndim * (Ndim + 1)];  // hop0 row-major, padded 49

    const int tid = threadIdx.x;
    const int pid = blockIdx.x;

    // ============ phase 1: transpose [B*2304, 33] -> g_M ============
    if (pid < (Bdim * NN) / PR) {              // 256 active CTAs
        const int b     = pid >> 6;
        const int chunk = pid & 63;
        const int row0  = chunk * PR;

        const float* src = trans + ((size_t)b * NN + row0) * Tdim;
        for (int i = tid; i < PR * Tdim; i += NTHREADS)
            P[i] = __ldg(src + i);             // fully coalesced
        __syncthreads();

        float* dst = g_M + (size_t)b * Tdim * NN + row0;
        for (int i = tid; i < PR * Tdim; i += NTHREADS) {
            const int t = i / PR;
            const int r = i - t * PR;
            dst[(size_t)t * NN + r] = P[r * Tdim + t];   // stride-33 smem: conflict-free
        }
    }
    grid_barrier(NBLOCKS);

    // ============ phase 2: max-plus DP, one CTA per (c,b) ============
    {
        const int c = pid % NCdim;
        const int b = pid / NCdim;

        const int tx  = tid % 12;              // col unit (4 wide)
        const int tyy = tid / 12;              // row unit (2 tall), 0..23
        const int col0 = tx * 4;
        const int row0 = tyy * 2;

        const int r0 = rules[c * 3 + 0];
        const int r1 = rules[c * 3 + 1];
        const int r2 = rules[c * 3 + 2];

        const float4* h0 = (const float4*)(g_M + (size_t)(b * Tdim + r0) * NN);
        const float4* h1 = (const float4*)(g_M + (size_t)(b * Tdim + r1) * NN);
        const float4* h2 = (const float4*)(g_M + (size_t)(b * Tdim + r2) * NN);

        float4* P4 = (float4*)P;
        float4* Q4 = (float4*)Q;
        float2* P2 = (float2*)P;
        float2* Q2 = (float2*)Q;

        // load hop0 -> padded tile, hop1 -> Q   (576 float4s, 2/thread)
        #pragma unroll
        for (int j = 0; j < 2; j++) {
            const int fi = tid + j * NTHREADS;
            const float4 v0 = h0[fi];
            Q4[fi] = h1[fi];
            const int flat = fi * 4;
            const int u = flat / Ndim;
            const int v = flat - u * Ndim;
            float* tp = &Tpad[u * (Ndim + 1) + v];
            tp[0] = v0.x; tp[1] = v0.y; tp[2] = v0.z; tp[3] = v0.w;
        }
        __syncthreads();

        // P = hop0^T
        #pragma unroll
        for (int j = 0; j < 2; j++) {
            const int fi = tid + j * NTHREADS;
            const int flat = fi * 4;
            const int u = flat / Ndim;
            const int v = flat - u * Ndim;
            P4[fi] = make_float4(Tpad[(v + 0) * (Ndim + 1) + u],
                                 Tpad[(v + 1) * (Ndim + 1) + u],
                                 Tpad[(v + 2) * (Ndim + 1) + u],
                                 Tpad[(v + 3) * (Ndim + 1) + u]);
        }
        __syncthreads();

        float a00=-INFINITY,a01=-INFINITY,a02=-INFINITY,a03=-INFINITY;
        float a10=-INFINITY,a11=-INFINITY,a12=-INFINITY,a13=-INFINITY;

        // ---- stage 1: S = hop0 (max-plus) hop1, prefetched ----
        {
            float2 av = P2[tyy];
            float4 bv = Q4[tx];
            #pragma unroll 8
            for (int k = 0; k < Ndim; k++) {
                const float2 ac = av;
                const float4 bc = bv;
                if (k + 1 < Ndim) {
                    av = P2[(k + 1) * 24 + tyy];
                    bv = Q4[(k + 1) * 12 + tx];
                }
                a00=fmaxf(a00,ac.x+bc.x); a01=fmaxf(a01,ac.x+bc.y); a02=fmaxf(a02,ac.x+bc.z); a03=fmaxf(a03,ac.x+bc.w);
                a10=fmaxf(a10,ac.y+bc.x); a11=fmaxf(a11,ac.y+bc.y); a12=fmaxf(a12,ac.y+bc.z); a13=fmaxf(a13,ac.y+bc.w);
            }
        }
        __syncthreads();   // all reads of P,Q done

        // write S^T into Q; reload P with hop2 (row-major)
        {
            float2* qst = (float2*)(Q + col0 * Ndim + row0);
            qst[0 * 24] = make_float2(a00, a10);
            qst[1 * 24] = make_float2(a01, a11);
            qst[2 * 24] = make_float2(a02, a12);
            qst[3 * 24] = make_float2(a03, a13);
        }
        #pragma unroll
        for (int j = 0; j < 2; j++)
            P4[tid + j * NTHREADS] = h2[tid + j * NTHREADS];
        __syncthreads();

        // ---- stage 2: out = exp( S (max-plus) hop2 ), prefetched ----
        a00=-INFINITY;a01=-INFINITY;a02=-INFINITY;a03=-INFINITY;
        a10=-INFINITY;a11=-INFINITY;a12=-INFINITY;a13=-INFINITY;

        {
            float2 av = Q2[tyy];
            float4 bv = P4[tx];
            #pragma unroll 8
            for (int k = 0; k < Ndim; k++) {
                const float2 ac = av;
                const float4 bc = bv;
                if (k + 1 < Ndim) {
                    av = Q2[(k + 1) * 24 + tyy];
                    bv = P4[(k + 1) * 12 + tx];
                }
                a00=fmaxf(a00,ac.x+bc.x); a01=fmaxf(a01,ac.x+bc.y); a02=fmaxf(a02,ac.x+bc.z); a03=fmaxf(a03,ac.x+bc.w);
                a10=fmaxf(a10,ac.y+bc.x); a11=fmaxf(a11,ac.y+bc.y); a12=fmaxf(a12,ac.y+bc.z); a13=fmaxf(a13,ac.y+bc.w);
            }
        }

        float* outp = g_scratch + ((size_t)b * NCdim + c) * NN;
        *(float4*)(outp + (row0 + 0) * Ndim + col0) = make_float4(__expf(a00), __expf(a01), __expf(a02), __expf(a03));
        *(float4*)(outp + (row0 + 1) * Ndim + col0) = make_float4(__expf(a10), __expf(a11), __expf(a12), __expf(a13));
    }
    grid_barrier(NBLOCKS);

    // ============ phase 3: combine + mask ============
    {
        const int gid = pid * NTHREADS + tid;       // 0 .. 92159
        if (gid < Bdim * NN * 4) {
            const int g   = gid & 3;                // triple group of 4
            const int bxy = gid >> 2;
            const int xy  = bxy % NN;
            const int b   = bxy / NN;

            const float* wp = weights + g * 20;
            const float* bp = biases  + g * 4;

            float acc0 = __ldg(bp + 0);
            float acc1 = __ldg(bp + 1);
            float acc2 = __ldg(bp + 2);
            float acc3 = __ldg(bp + 3);

            const float* sp = g_scratch + ((size_t)b * NCdim + g * 20) * NN + xy;
            #pragma unroll
            for (int j = 0; j < 5; j++) {
                acc0 = fmaf(sp[(j +  0) * NN], __ldg(wp + j +  0), acc0);
                acc1 = fmaf(sp[(j +  5) * NN], __ldg(wp + j +  5), acc1);
                acc2 = fmaf(sp[(j + 10) * NN], __ldg(wp + j + 10), acc2);
                acc3 = fmaf(sp[(j + 15) * NN], __ldg(wp + j + 15), acc3);
            }

            const int4 m = *(const int4*)(type_mask + (size_t)bxy * Rdim + g * 4);
            float4 o;
            o.x = (m.x == 0) ? acc0 : NEGV;
            o.y = (m.y == 0) ? acc1 : NEGV;
            o.z = (m.z == 0) ? acc2 : NEGV;
            o.w = (m.w == 0) ? acc3 : NEGV;
            *(float4*)(out + (size_t)bxy * Rdim + g * 4) = o;
        }
    }
}

extern "C" void kernel_launch(void* const* d_in, const int* in_sizes, int n_in,
                              void* d_out, int out_size)
{
    const float* transitions = (const float*)d_in[0];
    const int*   type_mask   = (const int*)  d_in[1];
    const int*   rules       = (const int*)  d_in[2];
    const float* weights     = (const float*)d_in[3];
    const float* biases      = (const float*)d_in[4];
    float* out = (float*)d_out;

    fused_kernel<<<NBLOCKS, NTHREADS>>>(transitions, rules, type_mask,
                                        weights, biases, out);
}

// round 9
// speedup vs baseline: 1.0523x; 1.0523x over previous
#include <cuda_runtime.h>
#include <math.h>

#define Bdim 4
#define Ndim 48
#define Rdim 16
#define Tdim 33
#define NCdim 80
#define NIdim 5
#define NN (Ndim * Ndim)          // 2304
#define NEGV -1000.0f
#define PREP_ROWS 16
#define HROWS 24                  // rows per dp CTA (half-split)

// g_M[b,t][u*48+v] = trans[b,u,v,t]
__device__ float g_M[Bdim * Tdim * NN];
// scratch: exp(path score) per [b, c, xy]
__device__ float g_scratch[Bdim * NCdim * NN];

// ---------------------------------------------------------------------------
// Kernel 0: streaming transpose [B*2304, 33] -> per-t rows. Fine-grained grid
// (576 CTAs) so latency is covered by parallelism.
__global__ __launch_bounds__(128) void prep_kernel(const float* __restrict__ trans)
{
    __shared__ float tile[PREP_ROWS * Tdim];   // 528 floats

    const int chunk = blockIdx.x;              // 0..143
    const int b     = blockIdx.y;
    const int tid   = threadIdx.x;
    const int row0  = chunk * PREP_ROWS;

    const float* src = trans + ((size_t)b * NN + row0) * Tdim;
    #pragma unroll
    for (int i = tid; i < PREP_ROWS * Tdim; i += 128)
        tile[i] = __ldg(src + i);              // fully coalesced
    __syncthreads();

    float* dst = g_M + (size_t)b * Tdim * NN + row0;
    #pragma unroll
    for (int i = tid; i < PREP_ROWS * Tdim; i += 128) {
        const int t = i >> 4;                  // /16
        const int r = i & 15;
        dst[(size_t)t * NN + r] = tile[r * Tdim + t];   // stride-33: conflict-free
    }
}

// ---------------------------------------------------------------------------
// Kernel 1: one CTA per (c, b, row-half). 288 threads, each owns a 1x4 output
// tile. Stage 1 computes S rows [rowbase, rowbase+24) only (exact row split).
__global__ __launch_bounds__(288) void dp_kernel(const int* __restrict__ rules)
{
    __shared__ float At[Ndim * HROWS];          // hop0^T slice: At[k*24 + r]
    __shared__ float Bs[NN];                    // hop1, then hop2
    __shared__ float St[Ndim * (HROWS + 1)];    // staging / S^T slice, pitch 25

    const int c = blockIdx.x;
    const int b = blockIdx.y;
    const int rowbase = blockIdx.z * HROWS;

    const int tid = threadIdx.x;
    const int tx  = tid % 12;                   // col unit (4 wide)
    const int ty  = tid / 12;                   // local row 0..23
    const int col0 = tx * 4;

    const int r0 = __ldg(rules + c * 3 + 0);
    const int r1 = __ldg(rules + c * 3 + 1);
    const int r2 = __ldg(rules + c * 3 + 2);

    const float4* h0 = (const float4*)(g_M + (size_t)(b * Tdim + r0) * NN + rowbase * Ndim);
    const float4* h1 = (const float4*)(g_M + (size_t)(b * Tdim + r1) * NN);
    const float4* h2 = (const float4*)(g_M + (size_t)(b * Tdim + r2) * NN);

    float4* Bs4 = (float4*)Bs;

    // load hop1 (full) -> Bs, hop0 slice (24x48) -> staging in St (pitch 49)
    #pragma unroll
    for (int j = 0; j < 2; j++)
        Bs4[tid + j * 288] = h1[tid + j * 288];
    {
        const float4 v = h0[tid];               // 288 float4 = 24x48 slice
        const int flat = tid * 4;
        const int r = flat / Ndim;
        const int k = flat - r * Ndim;
        float* tp = &St[r * 49 + k];
        tp[0] = v.x; tp[1] = v.y; tp[2] = v.z; tp[3] = v.w;
    }
    __syncthreads();

    // At[k*24 + r] = hop0[rowbase + r][k]
    #pragma unroll
    for (int j = 0; j < 4; j++) {
        const int idx = tid + j * 288;          // 0..1151
        const int k = idx / HROWS;
        const int r = idx - k * HROWS;
        At[idx] = St[r * 49 + k];
    }
    __syncthreads();

    // ---- stage 1: S[rowbase+ty][col0..+3] ----
    float a0 = -INFINITY, a1 = -INFINITY, a2 = -INFINITY, a3 = -INFINITY;
    #pragma unroll 8
    for (int k = 0; k < Ndim; k++) {
        const float  av = At[k * HROWS + ty];
        const float4 bv = Bs4[k * 12 + tx];
        a0 = fmaxf(a0, av + bv.x);
        a1 = fmaxf(a1, av + bv.y);
        a2 = fmaxf(a2, av + bv.z);
        a3 = fmaxf(a3, av + bv.w);
    }
    __syncthreads();                            // all reads of Bs/St done

    // write S^T slice (pitch 25), reload Bs with hop2
    St[(col0 + 0) * 25 + ty] = a0;
    St[(col0 + 1) * 25 + ty] = a1;
    St[(col0 + 2) * 25 + ty] = a2;
    St[(col0 + 3) * 25 + ty] = a3;
    #pragma unroll
    for (int j = 0; j < 2; j++)
        Bs4[tid + j * 288] = h2[tid + j * 288];
    __syncthreads();

    // ---- stage 2: out[rowbase+ty][col0..+3] = exp(max_k S + hop2) ----
    a0 = -INFINITY; a1 = -INFINITY; a2 = -INFINITY; a3 = -INFINITY;
    #pragma unroll 8
    for (int k = 0; k < Ndim; k++) {
        const float  av = St[k * 25 + ty];
        const float4 bv = Bs4[k * 12 + tx];
        a0 = fmaxf(a0, av + bv.x);
        a1 = fmaxf(a1, av + bv.y);
        a2 = fmaxf(a2, av + bv.z);
        a3 = fmaxf(a3, av + bv.w);
    }

    float* outp = g_scratch + ((size_t)b * NCdim + c) * NN + (rowbase + ty) * Ndim + col0;
    *(float4*)outp = make_float4(__expf(a0), __expf(a1), __expf(a2), __expf(a3));
}

// ---------------------------------------------------------------------------
// Kernel 2: one thread per (b, xy, group-of-4 triples). 20 coalesced chain
// loads per thread, int4 mask load + float4 store.
__global__ __launch_bounds__(256) void combine_kernel(const int*   __restrict__ type_mask,
                                                      const float* __restrict__ weights,
                                                      const float* __restrict__ biases,
                                                      float*       __restrict__ out)
{
    __shared__ float ws[NCdim];
    __shared__ float bs[Rdim];
    const int tid = threadIdx.x;
    if (tid < NCdim) ws[tid] = weights[tid];
    if (tid < Rdim)  bs[tid] = biases[tid];
    __syncthreads();

    const int idx = blockIdx.x * 256 + tid;   // 0 .. B*NN*4-1 (36864)
    const int g   = idx & 3;
    const int bxy = idx >> 2;
    const int xy  = bxy % NN;
    const int b   = bxy / NN;

    float acc0 = bs[g * 4 + 0];
    float acc1 = bs[g * 4 + 1];
    float acc2 = bs[g * 4 + 2];
    float acc3 = bs[g * 4 + 3];

    const float* sp = g_scratch + ((size_t)b * NCdim + g * 20) * NN + xy;
    const float* wp = ws + g * 20;
    #pragma unroll
    for (int j = 0; j < 5; j++) {
        acc0 = fmaf(sp[(j +  0) * NN], wp[j +  0], acc0);
        acc1 = fmaf(sp[(j +  5) * NN], wp[j +  5], acc1);
        acc2 = fmaf(sp[(j + 10) * NN], wp[j + 10], acc2);
        acc3 = fmaf(sp[(j + 15) * NN], wp[j + 15], acc3);
    }

    const int4 m = *(const int4*)(type_mask + (size_t)bxy * Rdim + g * 4);
    float4 o;
    o.x = (m.x == 0) ? acc0 : NEGV;
    o.y = (m.y == 0) ? acc1 : NEGV;
    o.z = (m.z == 0) ? acc2 : NEGV;
    o.w = (m.w == 0) ? acc3 : NEGV;
    *(float4*)(out + (size_t)bxy * Rdim + g * 4) = o;
}

extern "C" void kernel_launch(void* const* d_in, const int* in_sizes, int n_in,
                              void* d_out, int out_size)
{
    const float* transitions = (const float*)d_in[0];
    const int*   type_mask   = (const int*)  d_in[1];
    const int*   rules       = (const int*)  d_in[2];
    const float* weights     = (const float*)d_in[3];
    const float* biases      = (const float*)d_in[4];
    float* out = (float*)d_out;

    dim3 grid0(NN / PREP_ROWS, Bdim);          // (144, 4) = 576 CTAs
    prep_kernel<<<grid0, 128>>>(transitions);

    dim3 grid1(NCdim, Bdim, Ndim / HROWS);     // (80, 4, 2) = 640 CTAs
    dp_kernel<<<grid1, 288>>>(rules);

    combine_kernel<<<(Bdim * NN * 4) / 256, 256>>>(type_mask, weights, biases, out);
}

// round 10
// speedup vs baseline: 1.4274x; 1.3564x over previous
#include <cuda_runtime.h>
#include <math.h>

#define Bdim 4
#define Ndim 48
#define Rdim 16
#define Tdim 33
#define NCdim 80
#define NIdim 5
#define NN (Ndim * Ndim)          // 2304
#define NEGV -1000.0f
#define PREP_ROWS 32
#define HROWS 24                  // rows per dp CTA (z-split for tail balance)
#define PITCH 49                  // padded pitch: conflict-free row-major LDS.32

// g_M[b,t][u*48+v] = trans[b,u,v,t]
__device__ float g_M[Bdim * Tdim * NN];
// scratch: exp(path score) per [b, c, xy]
__device__ float g_scratch[Bdim * NCdim * NN];

// ---------------------------------------------------------------------------
// Kernel 0: streaming transpose [B*2304, 33] -> per-t rows.
// Coalesced scalar reads; stores are full 128B per warp (32 consecutive r).
__global__ __launch_bounds__(256) void prep_kernel(const float* __restrict__ trans)
{
    __shared__ float tile[PREP_ROWS * Tdim];   // 1056 floats

    const int chunk = blockIdx.x;              // 0..71
    const int b     = blockIdx.y;
    const int tid   = threadIdx.x;
    const int row0  = chunk * PREP_ROWS;

    const float* src = trans + ((size_t)b * NN + row0) * Tdim;
    #pragma unroll
    for (int i = tid; i < PREP_ROWS * Tdim; i += 256)
        tile[i] = __ldg(src + i);              // fully coalesced
    __syncthreads();

    float* dst = g_M + (size_t)b * Tdim * NN + row0;
    #pragma unroll
    for (int i = tid; i < PREP_ROWS * Tdim; i += 256) {
        const int t = i >> 5;                  // /32
        const int r = i & 31;
        dst[(size_t)t * NN + r] = tile[r * Tdim + t];   // stride-33 smem: conflict-free
    }
}

// ---------------------------------------------------------------------------
// Kernel 1: one CTA per (c, b, row-half). 144 threads: thread = (oct, xr),
// oct = column octet (0..5, warp-broadcast B reads), xr = local row (0..23,
// conflict-free pitch-49 A reads). 8 outputs per thread.
__global__ __launch_bounds__(144) void dp_kernel(const int* __restrict__ rules)
{
    __shared__ float A0[HROWS * PITCH];        // hop0 slice (pitch 49), then S
    __shared__ float B1[NN];                   // hop1 (full)
    __shared__ float B2[NN];                   // hop2 (full)

    const int c = blockIdx.x;
    const int b = blockIdx.y;
    const int rowbase = blockIdx.z * HROWS;

    const int tid = threadIdx.x;
    const int oct = tid / HROWS;               // 0..5
    const int xr  = tid - oct * HROWS;         // 0..23

    const int r0 = __ldg(rules + c * 3 + 0);
    const int r1 = __ldg(rules + c * 3 + 1);
    const int r2 = __ldg(rules + c * 3 + 2);

    const float*  h0 = g_M + (size_t)(b * Tdim + r0) * NN + rowbase * Ndim;
    const float4* h1 = (const float4*)(g_M + (size_t)(b * Tdim + r1) * NN);
    const float4* h2 = (const float4*)(g_M + (size_t)(b * Tdim + r2) * NN);

    // fills: B1/B2 full (float4, coalesced), hop0 slice into pitch-49 A0
    float4* B14 = (float4*)B1;
    float4* B24 = (float4*)B2;
    #pragma unroll
    for (int j = 0; j < 4; j++) {
        B14[tid + j * 144] = h1[tid + j * 144];
        B24[tid + j * 144] = h2[tid + j * 144];
    }
    #pragma unroll
    for (int i = tid; i < HROWS * Ndim; i += 144) {
        const int u = i / Ndim;
        const int v = i - u * Ndim;
        A0[u * PITCH + v] = h0[i];             // coalesced gmem read
    }
    __syncthreads();

    float a0, a1, a2, a3, a4, a5, a6, a7;
    a0 = a1 = a2 = a3 = a4 = a5 = a6 = a7 = -INFINITY;

    const float* ap  = A0 + xr * PITCH;
    const float* bp1 = B1 + oct * 8;

    // ---- stage 1: S[x][oct*8..+7] = max_k hop0[x][k] + hop1[k][..] ----
    #pragma unroll 8
    for (int k = 0; k < Ndim; k++) {
        const float  av  = ap[k];                              // conflict-free
        const float4 bv0 = *(const float4*)(bp1 + k * Ndim);   // warp-broadcast
        const float4 bv1 = *(const float4*)(bp1 + k * Ndim + 4);
        a0 = fmaxf(a0, av + bv0.x); a1 = fmaxf(a1, av + bv0.y);
        a2 = fmaxf(a2, av + bv0.z); a3 = fmaxf(a3, av + bv0.w);
        a4 = fmaxf(a4, av + bv1.x); a5 = fmaxf(a5, av + bv1.y);
        a6 = fmaxf(a6, av + bv1.z); a7 = fmaxf(a7, av + bv1.w);
    }
    __syncthreads();                           // all A0 reads done

    // write S into A0 (same pitch-49 layout)
    {
        float* sp = A0 + xr * PITCH + oct * 8;
        sp[0] = a0; sp[1] = a1; sp[2] = a2; sp[3] = a3;
        sp[4] = a4; sp[5] = a5; sp[6] = a6; sp[7] = a7;
    }
    __syncthreads();

    // ---- stage 2: out[x][oct*8..+7] = exp(max_k S[x][k] + hop2[k][..]) ----
    a0 = a1 = a2 = a3 = a4 = a5 = a6 = a7 = -INFINITY;
    const float* bp2 = B2 + oct * 8;

    #pragma unroll 8
    for (int k = 0; k < Ndim; k++) {
        const float  av  = ap[k];                              // S row, conflict-free
        const float4 bv0 = *(const float4*)(bp2 + k * Ndim);   // warp-broadcast
        const float4 bv1 = *(const float4*)(bp2 + k * Ndim + 4);
        a0 = fmaxf(a0, av + bv0.x); a1 = fmaxf(a1, av + bv0.y);
        a2 = fmaxf(a2, av + bv0.z); a3 = fmaxf(a3, av + bv0.w);
        a4 = fmaxf(a4, av + bv1.x); a5 = fmaxf(a5, av + bv1.y);
        a6 = fmaxf(a6, av + bv1.z); a7 = fmaxf(a7, av + bv1.w);
    }

    float* op = g_scratch + ((size_t)b * NCdim + c) * NN + (rowbase + xr) * Ndim + oct * 8;
    *(float4*)(op + 0) = make_float4(__expf(a0), __expf(a1), __expf(a2), __expf(a3));
    *(float4*)(op + 4) = make_float4(__expf(a4), __expf(a5), __expf(a6), __expf(a7));
}

// ---------------------------------------------------------------------------
// Kernel 2: one thread per (b, xy, group-of-4 triples). 20 coalesced chain
// loads per thread, int4 mask load + float4 store.
__global__ __launch_bounds__(256) void combine_kernel(const int*   __restrict__ type_mask,
                                                      const float* __restrict__ weights,
                                                      const float* __restrict__ biases,
                                                      float*       __restrict__ out)
{
    __shared__ float ws[NCdim];
    __shared__ float bs[Rdim];
    const int tid = threadIdx.x;
    if (tid < NCdim) ws[tid] = weights[tid];
    if (tid < Rdim)  bs[tid] = biases[tid];
    __syncthreads();

    const int idx = blockIdx.x * 256 + tid;   // 0 .. B*NN*4-1 (36864)
    const int g   = idx & 3;
    const int bxy = idx >> 2;
    const int xy  = bxy % NN;
    const int b   = bxy / NN;

    float acc0 = bs[g * 4 + 0];
    float acc1 = bs[g * 4 + 1];
    float acc2 = bs[g * 4 + 2];
    float acc3 = bs[g * 4 + 3];

    const float* sp = g_scratch + ((size_t)b * NCdim + g * 20) * NN + xy;
    const float* wp = ws + g * 20;
    #pragma unroll
    for (int j = 0; j < 5; j++) {
        acc0 = fmaf(sp[(j +  0) * NN], wp[j +  0], acc0);
        acc1 = fmaf(sp[(j +  5) * NN], wp[j +  5], acc1);
        acc2 = fmaf(sp[(j + 10) * NN], wp[j + 10], acc2);
        acc3 = fmaf(sp[(j + 15) * NN], wp[j + 15], acc3);
    }

    const int4 m = *(const int4*)(type_mask + (size_t)bxy * Rdim + g * 4);
    float4 o;
    o.x = (m.x == 0) ? acc0 : NEGV;
    o.y = (m.y == 0) ? acc1 : NEGV;
    o.z = (m.z == 0) ? acc2 : NEGV;
    o.w = (m.w == 0) ? acc3 : NEGV;
    *(float4*)(out + (size_t)bxy * Rdim + g * 4) = o;
}

extern "C" void kernel_launch(void* const* d_in, const int* in_sizes, int n_in,
                              void* d_out, int out_size)
{
    const float* transitions = (const float*)d_in[0];
    const int*   type_mask   = (const int*)  d_in[1];
    const int*   rules       = (const int*)  d_in[2];
    const float* weights     = (const float*)d_in[3];
    const float* biases      = (const float*)d_in[4];
    float* out = (float*)d_out;

    dim3 grid0(NN / PREP_ROWS, Bdim);          // (72, 4) = 288 CTAs
    prep_kernel<<<grid0, 256>>>(transitions);

    dim3 grid1(NCdim, Bdim, Ndim / HROWS);     // (80, 4, 2) = 640 CTAs
    dp_kernel<<<grid1, 144>>>(rules);

    combine_kernel<<<(Bdim * NN * 4) / 256, 256>>>(type_mask, weights, biases, out);
}